// round 12
// baseline (speedup 1.0000x reference)
#include <cuda_runtime.h>
#include <cstdint>

#define Vv 50000
#define Dd 300
#define Hh 512
#define Gg 2048
#define Bb 32
#define LCc 400
#define LQ1 29
#define NR 928
#define NEGLOGV -10.8197782844103f

__device__ __align__(16) float g_MT[2][150*4096];            // [which][d/2][g][d&1]
__device__ __align__(16) float g_xgE[(size_t)LCc*Bb*Gg];     // [(t*32+b)][g]
__device__ __align__(16) float g_xgD[(size_t)LQ1*Bb*Gg];
__device__ __align__(16) float g_h[2][Hh*Bb];                // [(k/2)*64 + b*2 + (k&1)]
__device__ __align__(16) float g_c[Hh*Bb];                   // [k*32+b]
__device__ __align__(16) float g_dech[NR*Hh];                // [(b*29+t)][k]
__device__ int g_clen[Bb];

__device__ __forceinline__ void fma2(unsigned long long &a, unsigned long long x, unsigned long long y){
    asm("fma.rn.f32x2 %0, %1, %2, %0;" : "+l"(a) : "l"(x), "l"(y));
}
__device__ __forceinline__ float2 up2(unsigned long long v){
    float2 f; asm("mov.b64 {%0,%1}, %2;" : "=f"(f.x), "=f"(f.y) : "l"(v)); return f;
}

__global__ void k_clen(const int* __restrict__ cw){
    int tid = threadIdx.x, b = tid>>3, sub = tid&7, s = 0;
    for (int t = sub; t < LCc; t += 8) s += (cw[b*LCc+t] != 0);
    __shared__ int r[256];
    r[tid] = s; __syncthreads();
    if (sub == 0){ int tot = 0;
        #pragma unroll
        for (int u = 0; u < 8; u++) tot += r[tid+u];
        g_clen[b] = tot; }
}

__global__ void k_zero(){
    int i = blockIdx.x*256 + threadIdx.x;
    if (i < Hh*Bb){ g_h[0][i] = 0.f; g_h[1][i] = 0.f; g_c[i] = 0.f; }
}

// M[g][d] = sum_h Wih[g][h]*embW[h][d], stored d-pair interleaved
__global__ void k_fuseM(const float* __restrict__ Wih, const float* __restrict__ embW, int which){
    __shared__ float ws[8*512];
    int tid = threadIdx.x, g0 = blockIdx.x*8;
    for (int i = tid; i < 4096; i += 320)
        ws[i] = Wih[(size_t)(g0 + (i>>9))*Hh + (i&511)];
    __syncthreads();
    if (tid < Dd){
        float acc[8];
        #pragma unroll
        for (int g = 0; g < 8; g++) acc[g] = 0.f;
        for (int h = 0; h < Hh; h++){
            float e = embW[h*Dd + tid];
            #pragma unroll
            for (int g = 0; g < 8; g++) acc[g] += ws[g*512+h]*e;
        }
        float* M = g_MT[which];
        int dd = tid>>1, lo = tid&1;
        #pragma unroll
        for (int g = 0; g < 8; g++) M[dd*4096 + (g0+g)*2 + lo] = acc[g];
    }
}

// xg for 16 rows (same t) per block; 256 thr, 4 passes x 2 g, 16-row acc
__global__ void k_xg(const int* __restrict__ idxs, int sstride,
                     const float* __restrict__ wv,
                     const float* __restrict__ bih, const float* __restrict__ bhh,
                     int which){
    __shared__ __align__(16) float wvs[16*304];
    __shared__ int sidx[16];
    int tid = threadIdx.x;
    int row16 = blockIdx.x*16, t = row16>>5, b0 = row16&31;
    if (tid < 16) sidx[tid] = idxs[(b0+tid)*sstride + t];
    __syncthreads();
    const float4* wv4 = (const float4*)wv;
    for (int i = tid; i < 1200; i += 256){
        int r = i/75, d4 = i - r*75;
        *(float4*)&wvs[r*304 + d4*4] = wv4[(size_t)sidx[r]*75 + d4];
    }
    __syncthreads();
    const unsigned long long* Mu = (const unsigned long long*)g_MT[which];
    const unsigned long long* wu = (const unsigned long long*)wvs;
    float* xg = which ? g_xgD : g_xgE;
    for (int pass = 0; pass < 4; pass++){
        unsigned long long a0[16], a1[16];
        #pragma unroll
        for (int r = 0; r < 16; r++){ a0[r] = 0ULL; a1[r] = 0ULL; }
        int g = pass*512 + tid;
        for (int dd = 0; dd < 150; dd++){
            unsigned long long m0 = Mu[dd*2048 + g];
            unsigned long long m1 = Mu[dd*2048 + g + 256];
            #pragma unroll
            for (int r = 0; r < 16; r++){
                unsigned long long w2 = wu[r*152 + dd];
                fma2(a0[r], m0, w2);
                fma2(a1[r], m1, w2);
            }
        }
        float bs0 = bih[g] + bhh[g], bs1 = bih[g+256] + bhh[g+256];
        #pragma unroll
        for (int r = 0; r < 16; r++){
            float2 f0 = up2(a0[r]), f1 = up2(a1[r]);
            size_t base = (size_t)(t*32 + b0 + r)*Gg;
            xg[base + g] = f0.x + f0.y + bs0;
            xg[base + g + 256] = f1.x + f1.y + bs1;
        }
    }
}

// one LSTM step: block owns k in [bid*4, bid*4+4), all 4 gates (16 rows)
__global__ void k_step(const float* __restrict__ whh, int which, int t, int parity,
                       int use_mask, int store_dech){
    __shared__ __align__(16) float ws[16*512];
    __shared__ float sacc[16*32];
    int tid = threadIdx.x, k0 = blockIdx.x*4;
    const float4* w4 = (const float4*)whh;
    float4* ws4 = (float4*)ws;
    for (int i = tid; i < 2048; i += 256){
        int rr = i>>7, j4 = i&127;
        ws4[i] = w4[(size_t)((rr>>2)*Hh + k0 + (rr&3))*128 + j4];
    }
    const float* h_in = g_h[parity];
    float* h_out = g_h[parity^1];
    const float* xg_t = (which ? g_xgD : g_xgE);
    __syncthreads();
    int b = tid&31, rr2 = tid>>5;
    const unsigned long long* h2 = (const unsigned long long*)h_in;
    const unsigned long long* wsu = (const unsigned long long*)ws;
    unsigned long long a0 = 0ULL, a1 = 0ULL;
    int r0 = rr2*2;
    #pragma unroll 4
    for (int jj = 0; jj < 256; jj++){
        unsigned long long hv = h2[jj*32 + b];
        fma2(a0, wsu[r0*256 + jj], hv);
        fma2(a1, wsu[(r0+1)*256 + jj], hv);
    }
    float2 f0 = up2(a0), f1 = up2(a1);
    sacc[r0*32 + b] = f0.x + f0.y;
    sacc[(r0+1)*32 + b] = f1.x + f1.y;
    __syncthreads();
    if (tid < 128){
        int kk = tid>>5, k = k0 + kk;
        size_t xbase = (size_t)(t*32 + b)*Gg;
        float vi = xg_t[xbase + k]        + sacc[(0*4+kk)*32 + b];
        float vf = xg_t[xbase + 512 + k]  + sacc[(1*4+kk)*32 + b];
        float vg = xg_t[xbase + 1024 + k] + sacc[(2*4+kk)*32 + b];
        float vo = xg_t[xbase + 1536 + k] + sacc[(3*4+kk)*32 + b];
        float ig = 1.f/(1.f + expf(-vi));
        float fg = 1.f/(1.f + expf(-vf));
        float gg = tanhf(vg);
        float og = 1.f/(1.f + expf(-vo));
        int cidx = k*32 + b;
        float cp = g_c[cidx];
        float nc = fg*cp + ig*gg;
        float nh = og*tanhf(nc);
        int hidx = (k>>1)*64 + b*2 + (k&1);
        if (use_mask && t >= g_clen[b]){ nh = h_in[hidx]; nc = cp; }
        g_c[cidx] = nc;
        h_out[hidx] = nh;
        if (store_dech) g_dech[(size_t)(b*LQ1 + t)*Hh + k] = nh;
    }
}

// GEMM: logits[row][v] = dech[row]·pW[v] + pb[v]; block = 32 rows x 256 v
__global__ void k_proj(const float* __restrict__ pW, const float* __restrict__ pb,
                       float* __restrict__ out){
    __shared__ __align__(16) float As[32*36];
    __shared__ __align__(16) float Bs[256*34];
    int tid = threadIdx.x;
    int row0 = blockIdx.y*32, v0 = blockIdx.x*256;
    int vg = tid&31, rgrp = tid>>5;
    unsigned long long acc[4][8];
    #pragma unroll
    for (int r = 0; r < 4; r++)
        #pragma unroll
        for (int v = 0; v < 8; v++) acc[r][v] = 0ULL;
    const float4* pW4 = (const float4*)pW;
    for (int kc = 0; kc < Hh; kc += 32){
        __syncthreads();
        for (int i = tid; i < 1024; i += 256)
            As[(i>>5)*36 + (i&31)] = g_dech[(size_t)(row0 + (i>>5))*Hh + kc + (i&31)];
        for (int i = tid; i < 2048; i += 256){
            int vv = i>>3, q = i&7, v = v0 + vv;
            float4 val = (v < Vv) ? pW4[(size_t)v*128 + (kc>>2) + q]
                                  : make_float4(0.f,0.f,0.f,0.f);
            unsigned long long* dst = (unsigned long long*)Bs + (size_t)vv*17 + q*2;
            dst[0] = ((const ulonglong2*)&val)->x;
            dst[1] = ((const ulonglong2*)&val)->y;
        }
        __syncthreads();
        const unsigned long long* Au = (const unsigned long long*)As;
        const unsigned long long* Bu = (const unsigned long long*)Bs;
        #pragma unroll 4
        for (int kk = 0; kk < 16; kk++){
            unsigned long long a2[4], b2[8];
            #pragma unroll
            for (int r = 0; r < 4; r++) a2[r] = Au[(rgrp*4 + r)*18 + kk];
            #pragma unroll
            for (int v = 0; v < 8; v++) b2[v] = Bu[(vg + 32*v)*17 + kk];
            #pragma unroll
            for (int r = 0; r < 4; r++)
                #pragma unroll
                for (int v = 0; v < 8; v++) fma2(acc[r][v], a2[r], b2[v]);
        }
    }
    #pragma unroll
    for (int r = 0; r < 4; r++){
        int row = row0 + rgrp*4 + r;
        #pragma unroll
        for (int v = 0; v < 8; v++){
            int vc = v0 + vg + 32*v;
            if (vc < Vv){
                float2 f = up2(acc[r][v]);
                out[(size_t)row*Vv + vc] = f.x + f.y + pb[vc];
            }
        }
    }
}

__global__ void k_softmax(const int* __restrict__ qw, float* __restrict__ out){
    int row = blockIdx.x, tid = threadIdx.x;
    int b = row/LQ1, t = row - b*LQ1;
    float* p = out + (size_t)row*Vv;
    float4* p4 = (float4*)p;
    if (qw[b*30 + t] == 0){
        float4 fill = make_float4(NEGLOGV, NEGLOGV, NEGLOGV, NEGLOGV);
        for (int i = tid; i < 12500; i += 256) p4[i] = fill;
        return;
    }
    __shared__ float red[256];
    float m = -1e30f;
    for (int i = tid; i < 12500; i += 256){
        float4 x = p4[i];
        m = fmaxf(m, fmaxf(fmaxf(x.x, x.y), fmaxf(x.z, x.w)));
    }
    red[tid] = m; __syncthreads();
    for (int s = 128; s > 0; s >>= 1){
        if (tid < s) red[tid] = fmaxf(red[tid], red[tid+s]);
        __syncthreads();
    }
    m = red[0]; __syncthreads();
    float sum = 0.f;
    for (int i = tid; i < 12500; i += 256){
        float4 x = p4[i];
        sum += __expf(x.x - m) + __expf(x.y - m) + __expf(x.z - m) + __expf(x.w - m);
    }
    red[tid] = sum; __syncthreads();
    for (int s = 128; s > 0; s >>= 1){
        if (tid < s) red[tid] += red[tid+s];
        __syncthreads();
    }
    float lse = m + logf(red[0]);
    __syncthreads();
    for (int i = tid; i < 12500; i += 256){
        float4 x = p4[i];
        x.x -= lse; x.y -= lse; x.z -= lse; x.w -= lse;
        p4[i] = x;
    }
}

extern "C" void kernel_launch(void* const* d_in, const int* in_sizes, int n_in,
                              void* d_out, int out_size){
    const int*   cw   = (const int*)d_in[0];
    const int*   qw   = (const int*)d_in[1];
    const float* wv   = (const float*)d_in[2];
    const float* embW = (const float*)d_in[3];
    const float* eWih = (const float*)d_in[4];
    const float* eWhh = (const float*)d_in[5];
    const float* ebih = (const float*)d_in[6];
    const float* ebhh = (const float*)d_in[7];
    const float* dWih = (const float*)d_in[8];
    const float* dWhh = (const float*)d_in[9];
    const float* dbih = (const float*)d_in[10];
    const float* dbhh = (const float*)d_in[11];
    const float* pW   = (const float*)d_in[12];
    const float* pb   = (const float*)d_in[13];
    float* out = (float*)d_out;

    k_clen<<<1, 256>>>(cw);
    k_zero<<<64, 256>>>();
    k_fuseM<<<256, 320>>>(eWih, embW, 0);
    k_fuseM<<<256, 320>>>(dWih, embW, 1);
    k_xg<<<800, 256>>>(cw, LCc, wv, ebih, ebhh, 0);
    k_xg<<<58, 256>>>(qw, 30, wv, dbih, dbhh, 1);
    for (int t = 0; t < LCc; t++)
        k_step<<<128, 256>>>(eWhh, 0, t, t&1, 1, 0);
    for (int t = 0; t < LQ1; t++)
        k_step<<<128, 256>>>(dWhh, 1, t, (LCc + t)&1, 0, 1);
    k_proj<<<dim3(196, 29), 256>>>(pW, pb, out);
    k_softmax<<<NR, 256>>>(qw, out);
}

// round 13
// speedup vs baseline: 1.5905x; 1.5905x over previous
#include <cuda_runtime.h>
#include <cstdint>

#define Vv 50000
#define Dd 300
#define Hh 512
#define Gg 2048
#define Bb 32
#define LCc 400
#define LQ1 29
#define NR 928
#define NEGLOGV -10.8197782844103f

// ---------------- device scratch ----------------
__device__ __align__(16) float g_MT[2][150*4096];            // [which][d/2][g][d&1]
__device__ __align__(16) float g_xgE[(size_t)LCc*Gg*Bb];     // [t][g][b]
__device__ __align__(16) float g_xgD[(size_t)LQ1*Gg*Bb];     // [t][g][b]
__device__ __align__(16) float g_h[2][Hh*Bb];                // quad layout: [(k>>2)*128 + b*4 + (k&3)]
__device__ __align__(16) float g_c[Hh*Bb];                   // [k*32+b]
__device__ __align__(16) float g_dech[NR*Hh];                // [(b*29+t)][k]
__device__ int g_clen[Bb];
__device__ unsigned g_bar_count;
__device__ unsigned g_bar_sense;

// ---------------- helpers ----------------
__device__ __forceinline__ void fma2(unsigned long long &a, unsigned long long x, unsigned long long y){
    asm("fma.rn.f32x2 %0, %1, %2, %0;" : "+l"(a) : "l"(x), "l"(y));
}
__device__ __forceinline__ float2 up2(unsigned long long v){
    float2 f; asm("mov.b64 {%0,%1}, %2;" : "=f"(f.x), "=f"(f.y) : "l"(v)); return f;
}
__device__ __forceinline__ ulonglong2 ldcg128(const ulonglong2* p){
    ulonglong2 r;
    asm volatile("ld.global.cg.v2.u64 {%0,%1},[%2];" : "=l"(r.x), "=l"(r.y) : "l"(p));
    return r;
}
__device__ __forceinline__ unsigned ldvol(const unsigned* p){
    unsigned v;
    asm volatile("ld.volatile.global.u32 %0,[%1];" : "=r"(v) : "l"(p));
    return v;
}

__global__ void k_clen(const int* __restrict__ cw){
    int tid = threadIdx.x, b = tid>>3, sub = tid&7, s = 0;
    for (int t = sub; t < LCc; t += 8) s += (cw[b*LCc+t] != 0);
    __shared__ int r[256];
    r[tid] = s; __syncthreads();
    if (sub == 0){ int tot = 0;
        #pragma unroll
        for (int u = 0; u < 8; u++) tot += r[tid+u];
        g_clen[b] = tot; }
}

__global__ void k_zero(){
    int i = blockIdx.x*256 + threadIdx.x;
    if (i < Hh*Bb){ g_h[0][i] = 0.f; g_h[1][i] = 0.f; g_c[i] = 0.f; }
    if (i == 0){ g_bar_count = 0u; g_bar_sense = 0u; }
}

// M[g][d] = sum_h Wih[g][h]*embW[h][d], stored d-pair interleaved
__global__ void k_fuseM(const float* __restrict__ Wih, const float* __restrict__ embW, int which){
    __shared__ float ws[8*512];
    int tid = threadIdx.x, g0 = blockIdx.x*8;
    for (int i = tid; i < 4096; i += 320)
        ws[i] = Wih[(size_t)(g0 + (i>>9))*Hh + (i&511)];
    __syncthreads();
    if (tid < Dd){
        float acc[8];
        #pragma unroll
        for (int g = 0; g < 8; g++) acc[g] = 0.f;
        for (int h = 0; h < Hh; h++){
            float e = embW[h*Dd + tid];
            #pragma unroll
            for (int g = 0; g < 8; g++) acc[g] += ws[g*512+h]*e;
        }
        float* M = g_MT[which];
        int dd = tid>>1, lo = tid&1;
        #pragma unroll
        for (int g = 0; g < 8; g++) M[dd*4096 + (g0+g)*2 + lo] = acc[g];
    }
}

// xg for 16 rows (same t) per block; writes [t][g][b] (coalesced reads in k_persist)
__global__ void k_xg(const int* __restrict__ idxs, int sstride,
                     const float* __restrict__ wv,
                     const float* __restrict__ bih, const float* __restrict__ bhh,
                     int which){
    __shared__ __align__(16) float wvs[16*304];
    __shared__ int sidx[16];
    int tid = threadIdx.x;
    int row16 = blockIdx.x*16, t = row16>>5, b0 = row16&31;
    if (tid < 16) sidx[tid] = idxs[(b0+tid)*sstride + t];
    __syncthreads();
    const float4* wv4 = (const float4*)wv;
    for (int i = tid; i < 1200; i += 256){
        int r = i/75, d4 = i - r*75;
        *(float4*)&wvs[r*304 + d4*4] = wv4[(size_t)sidx[r]*75 + d4];
    }
    __syncthreads();
    const unsigned long long* Mu = (const unsigned long long*)g_MT[which];
    const unsigned long long* wu = (const unsigned long long*)wvs;
    float* xg = which ? g_xgD : g_xgE;
    for (int pass = 0; pass < 4; pass++){
        unsigned long long a0[16], a1[16];
        #pragma unroll
        for (int r = 0; r < 16; r++){ a0[r] = 0ULL; a1[r] = 0ULL; }
        int g = pass*512 + tid;
        for (int dd = 0; dd < 150; dd++){
            unsigned long long m0 = Mu[dd*2048 + g];
            unsigned long long m1 = Mu[dd*2048 + g + 256];
            #pragma unroll
            for (int r = 0; r < 16; r++){
                unsigned long long w2 = wu[r*152 + dd];
                fma2(a0[r], m0, w2);
                fma2(a1[r], m1, w2);
            }
        }
        float bs0 = bih[g] + bhh[g], bs1 = bih[g+256] + bhh[g+256];
        size_t base0 = ((size_t)t*Gg + g)*Bb + b0;
        size_t base1 = ((size_t)t*Gg + g + 256)*Bb + b0;
        #pragma unroll
        for (int r = 0; r < 16; r++){
            float2 f0 = up2(a0[r]), f1 = up2(a1[r]);
            xg[base0 + r] = f0.x + f0.y + bs0;
            xg[base1 + r] = f1.x + f1.y + bs1;
        }
    }
}

// ---------------- persistent LSTM: all steps in one launch ----------------
// grid 128 blocks x 256 thr (all co-resident on 148 SMs). Block kg owns k = kg*4..+3.
// smem: ws[16*512] Whh rows (loaded once) | hs padded h stage | sacc reduce.
#define HS_OFF   (16*512)                 // floats
#define HS_SZ    (128*33*4)               // u2-padded: [jj4][b] stride 33 u2
#define SACC_OFF (HS_OFF + HS_SZ)
#define SMEM_PERSIST ((SACC_OFF + 512)*4) // bytes

__global__ void __launch_bounds__(256, 1)
k_persist(const float* __restrict__ whh, int which, int nsteps, int p0,
          int use_mask, int store_dech, unsigned bar_base){
    extern __shared__ __align__(16) float dsm[];
    float* ws = dsm;
    float* hs = dsm + HS_OFF;
    float* sacc = dsm + SACC_OFF;
    int tid = threadIdx.x, kg = blockIdx.x, k0 = kg*4;

    // stage Whh rows once: row rr = gate*4 + klocal
    const float4* w4 = (const float4*)whh;
    float4* ws4 = (float4*)ws;
    for (int i = tid; i < 2048; i += 256){
        int rr = i>>7, j4 = i&127;
        ws4[i] = w4[(size_t)((rr>>2)*Hh + k0 + (rr&3))*128 + j4];
    }

    // per-thread persistent state (tid<128): (kk,b) cell
    int b = tid&31;
    float c_reg = 0.f, h_own = 0.f;
    int mylen = 0x7fffffff, k = 0, kk = 0;
    if (tid < 128){
        kk = tid>>5; k = k0 + kk;
        c_reg = g_c[k*32 + b];
        h_own = g_h[p0][kg*128 + b*4 + kk];
        if (use_mask) mylen = g_clen[b];
    }
    const float* xg = which ? g_xgD : g_xgE;
    int rr2 = tid>>5, r0 = rr2*2;
    const ulonglong2* wsU = (const ulonglong2*)ws;
    ulonglong2* hsU = (ulonglong2*)hs;
    __syncthreads();

    int p = p0;
    for (int t = 0; t < nsteps; t++){
        // stage h(p) into smem (L1-bypass; other SMs wrote it)
        const ulonglong2* hg = (const ulonglong2*)g_h[p];
        for (int i = tid; i < 4096; i += 256)
            hsU[(i>>5)*33 + (i&31)] = ldcg128(&hg[i]);
        __syncthreads();

        // gates GEMV: rows r0, r0+1 (of 16), batch b
        unsigned long long a0 = 0ULL, a1 = 0ULL;
        #pragma unroll 4
        for (int jj4 = 0; jj4 < 128; jj4++){
            ulonglong2 hv = hsU[jj4*33 + b];
            ulonglong2 w0 = wsU[r0*128 + jj4];
            ulonglong2 w1 = wsU[(r0+1)*128 + jj4];
            fma2(a0, w0.x, hv.x); fma2(a0, w0.y, hv.y);
            fma2(a1, w1.x, hv.x); fma2(a1, w1.y, hv.y);
        }
        float2 f0 = up2(a0), f1 = up2(a1);
        sacc[r0*32 + b] = f0.x + f0.y;
        sacc[(r0+1)*32 + b] = f1.x + f1.y;
        __syncthreads();

        if (tid < 128){
            size_t xb = ((size_t)t*Gg)*Bb + (size_t)k*Bb + b;
            float vi = xg[xb]            + sacc[(0*4+kk)*32 + b];
            float vf = xg[xb + 512*Bb]   + sacc[(1*4+kk)*32 + b];
            float vg = xg[xb + 1024*Bb]  + sacc[(2*4+kk)*32 + b];
            float vo = xg[xb + 1536*Bb]  + sacc[(3*4+kk)*32 + b];
            float ig = 1.f/(1.f + expf(-vi));
            float fg = 1.f/(1.f + expf(-vf));
            float gg = tanhf(vg);
            float og = 1.f/(1.f + expf(-vo));
            float nc = fg*c_reg + ig*gg;
            float nh = og*tanhf(nc);
            if (t < mylen){ c_reg = nc; h_own = nh; }   // else frozen
            g_h[p^1][kg*128 + b*4 + kk] = h_own;
            if (store_dech) g_dech[(size_t)(b*LQ1 + t)*Hh + k] = h_own;
            __threadfence();
        }
        __syncthreads();

        // grid barrier (cumulative count, no reset race)
        if (tid == 0){
            unsigned target = bar_base + (unsigned)t + 1u;
            unsigned arrive = atomicAdd(&g_bar_count, 1u) + 1u;
            if (arrive == target*128u){
                atomicExch(&g_bar_sense, target);
            } else {
                while (ldvol(&g_bar_sense) < target) {}
            }
            __threadfence();
        }
        __syncthreads();
        p ^= 1;
    }
    if (tid < 128) g_c[k*32 + b] = c_reg;
}

// GEMM: logits[row][v] = dech[row]·pW[v] + pb[v]; block = 32 rows x 256 v
__global__ void __launch_bounds__(256)
k_proj(const float* __restrict__ pW, const float* __restrict__ pb,
       float* __restrict__ out){
    __shared__ __align__(16) float As[32*36];
    __shared__ __align__(16) float Bs[256*36];
    int tid = threadIdx.x;
    int row0 = blockIdx.y*32, v0 = blockIdx.x*256;
    int vg = tid&31, rgrp = tid>>5;
    unsigned long long acc[4][8];
    #pragma unroll
    for (int r = 0; r < 4; r++)
        #pragma unroll
        for (int v = 0; v < 8; v++) acc[r][v] = 0ULL;
    const float4* pW4 = (const float4*)pW;
    for (int kc = 0; kc < Hh; kc += 32){
        __syncthreads();
        for (int i = tid; i < 1024; i += 256)
            As[(i>>5)*36 + (i&31)] = g_dech[(size_t)(row0 + (i>>5))*Hh + kc + (i&31)];
        for (int i = tid; i < 2048; i += 256){
            int vv = i>>3, q = i&7, v = v0 + vv;
            float4 val = (v < Vv) ? pW4[(size_t)v*128 + (kc>>2) + q]
                                  : make_float4(0.f,0.f,0.f,0.f);
            ulonglong2* dst = (ulonglong2*)Bs + (size_t)vv*9 + q;
            *dst = *(const ulonglong2*)&val;
        }
        __syncthreads();
        const ulonglong2* Au = (const ulonglong2*)As;
        const ulonglong2* Bu = (const ulonglong2*)Bs;
        #pragma unroll
        for (int kk2 = 0; kk2 < 8; kk2++){
            ulonglong2 a2[4], b2[8];
            #pragma unroll
            for (int r = 0; r < 4; r++) a2[r] = Au[(rgrp*4 + r)*9 + kk2];
            #pragma unroll
            for (int v = 0; v < 8; v++) b2[v] = Bu[(vg + 32*v)*9 + kk2];
            #pragma unroll
            for (int r = 0; r < 4; r++)
                #pragma unroll
                for (int v = 0; v < 8; v++){
                    fma2(acc[r][v], a2[r].x, b2[v].x);
                    fma2(acc[r][v], a2[r].y, b2[v].y);
                }
        }
    }
    #pragma unroll
    for (int r = 0; r < 4; r++){
        int row = row0 + rgrp*4 + r;
        #pragma unroll
        for (int v = 0; v < 8; v++){
            int vc = v0 + vg + 32*v;
            if (vc < Vv){
                float2 f = up2(acc[r][v]);
                out[(size_t)row*Vv + vc] = f.x + f.y + pb[vc];
            }
        }
    }
}

__global__ void k_softmax(const int* __restrict__ qw, float* __restrict__ out){
    int row = blockIdx.x, tid = threadIdx.x;
    int b = row/LQ1, t = row - b*LQ1;
    float* p = out + (size_t)row*Vv;
    float4* p4 = (float4*)p;
    if (qw[b*30 + t] == 0){
        float4 fill = make_float4(NEGLOGV, NEGLOGV, NEGLOGV, NEGLOGV);
        for (int i = tid; i < 12500; i += 256) p4[i] = fill;
        return;
    }
    __shared__ float red[256];
    float m = -1e30f;
    for (int i = tid; i < 12500; i += 256){
        float4 x = p4[i];
        m = fmaxf(m, fmaxf(fmaxf(x.x, x.y), fmaxf(x.z, x.w)));
    }
    red[tid] = m; __syncthreads();
    for (int s = 128; s > 0; s >>= 1){
        if (tid < s) red[tid] = fmaxf(red[tid], red[tid+s]);
        __syncthreads();
    }
    m = red[0]; __syncthreads();
    float sum = 0.f;
    for (int i = tid; i < 12500; i += 256){
        float4 x = p4[i];
        sum += __expf(x.x - m) + __expf(x.y - m) + __expf(x.z - m) + __expf(x.w - m);
    }
    red[tid] = sum; __syncthreads();
    for (int s = 128; s > 0; s >>= 1){
        if (tid < s) red[tid] += red[tid+s];
        __syncthreads();
    }
    float lse = m + logf(red[0]);
    __syncthreads();
    for (int i = tid; i < 12500; i += 256){
        float4 x = p4[i];
        x.x -= lse; x.y -= lse; x.z -= lse; x.w -= lse;
        p4[i] = x;
    }
}

extern "C" void kernel_launch(void* const* d_in, const int* in_sizes, int n_in,
                              void* d_out, int out_size){
    const int*   cw   = (const int*)d_in[0];
    const int*   qw   = (const int*)d_in[1];
    const float* wv   = (const float*)d_in[2];
    const float* embW = (const float*)d_in[3];
    const float* eWih = (const float*)d_in[4];
    const float* eWhh = (const float*)d_in[5];
    const float* ebih = (const float*)d_in[6];
    const float* ebhh = (const float*)d_in[7];
    const float* dWih = (const float*)d_in[8];
    const float* dWhh = (const float*)d_in[9];
    const float* dbih = (const float*)d_in[10];
    const float* dbhh = (const float*)d_in[11];
    const float* pW   = (const float*)d_in[12];
    const float* pb   = (const float*)d_in[13];
    float* out = (float*)d_out;

    static int smem_set = 0;
    if (!smem_set){
        cudaFuncSetAttribute(k_persist, cudaFuncAttributeMaxDynamicSharedMemorySize, SMEM_PERSIST);
        smem_set = 1;
    }

    k_clen<<<1, 256>>>(cw);
    k_zero<<<64, 256>>>();
    k_fuseM<<<256, 320>>>(eWih, embW, 0);
    k_fuseM<<<256, 320>>>(dWih, embW, 1);
    k_xg<<<800, 256>>>(cw, LCc, wv, ebih, ebhh, 0);
    k_xg<<<58, 256>>>(qw, 30, wv, dbih, dbhh, 1);
    // encoder: 400 steps, masked; decoder: 29 steps, stores dech
    k_persist<<<128, 256, SMEM_PERSIST>>>(eWhh, 0, LCc, 0, 1, 0, 0u);
    k_persist<<<128, 256, SMEM_PERSIST>>>(dWhh, 1, LQ1, LCc & 1, 0, 1, (unsigned)LCc);
    k_proj<<<dim3(196, 29), 256>>>(pW, pb, out);
    k_softmax<<<NR, 256>>>(qw, out);
}

// round 14
// speedup vs baseline: 1.9016x; 1.1956x over previous
#include <cuda_runtime.h>
#include <cstdint>

#define Vv 50000
#define Dd 300
#define Hh 512
#define Gg 2048
#define Bb 32
#define LCc 400
#define LQ1 29
#define NR 928
#define NRPAD 960
#define GRIDP 128u
#define NEGLOGV -10.8197782844103f

// ---------------- device scratch ----------------
__device__ __align__(16) float g_MT[2][150*4096];            // [which][d/2][g][d&1]
__device__ __align__(16) float g_xgE[(size_t)LCc*Gg*Bb];     // [t][g][b]
__device__ __align__(16) float g_xgD[(size_t)LQ1*Gg*Bb];     // [t][g][b]
__device__ __align__(16) float g_h[2][Hh*Bb];                // quad layout: [(k>>2)*128 + b*4 + (k&3)]
__device__ __align__(16) float g_c[Hh*Bb];                   // [k*32+b]
__device__ __align__(16) float g_dech[(size_t)NRPAD*Hh];     // [(b*29+t)][k], padded rows
__device__ int g_clen[Bb];
__device__ unsigned g_bar_count;
__device__ unsigned g_bar_sense;

// ---------------- helpers ----------------
__device__ __forceinline__ void fma2(unsigned long long &a, unsigned long long x, unsigned long long y){
    asm("fma.rn.f32x2 %0, %1, %2, %0;" : "+l"(a) : "l"(x), "l"(y));
}
__device__ __forceinline__ float2 up2(unsigned long long v){
    float2 f; asm("mov.b64 {%0,%1}, %2;" : "=f"(f.x), "=f"(f.y) : "l"(v)); return f;
}
__device__ __forceinline__ unsigned long long pack2(float x){
    unsigned long long r; asm("mov.b64 %0, {%1, %1};" : "=l"(r) : "f"(x)); return r;
}
__device__ __forceinline__ ulonglong2 ldcg128(const ulonglong2* p){
    ulonglong2 r;
    asm volatile("ld.global.cg.v2.u64 {%0,%1},[%2];" : "=l"(r.x), "=l"(r.y) : "l"(p));
    return r;
}
__device__ __forceinline__ unsigned ldvol(const unsigned* p){
    unsigned v;
    asm volatile("ld.volatile.global.u32 %0,[%1];" : "=r"(v) : "l"(p));
    return v;
}

__global__ void k_clen(const int* __restrict__ cw){
    int tid = threadIdx.x, b = tid>>3, sub = tid&7, s = 0;
    for (int t = sub; t < LCc; t += 8) s += (cw[b*LCc+t] != 0);
    __shared__ int r[256];
    r[tid] = s; __syncthreads();
    if (sub == 0){ int tot = 0;
        #pragma unroll
        for (int u = 0; u < 8; u++) tot += r[tid+u];
        g_clen[b] = tot; }
}

__global__ void k_zero(){
    int i = blockIdx.x*256 + threadIdx.x;
    if (i < Hh*Bb){ g_h[0][i] = 0.f; g_h[1][i] = 0.f; g_c[i] = 0.f; }
    if (i == 0){ g_bar_count = 0u; g_bar_sense = 0u; }
}

// M[g][d] = sum_h Wih[g][h]*embW[h][d], g-pair FMA2, smem layout [h][g]
__global__ void k_fuseM(const float* __restrict__ Wih, const float* __restrict__ embW, int which){
    __shared__ __align__(16) float ws[512*8];
    int tid = threadIdx.x, g0 = blockIdx.x*8;
    for (int i = tid; i < 4096; i += 320)
        ws[(i&511)*8 + (i>>9)] = Wih[(size_t)(g0 + (i>>9))*Hh + (i&511)];
    __syncthreads();
    if (tid < Dd){
        unsigned long long acc2[4] = {0ULL,0ULL,0ULL,0ULL};
        const unsigned long long* wsu = (const unsigned long long*)ws;
        for (int h = 0; h < Hh; h++){
            unsigned long long e2 = pack2(embW[h*Dd + tid]);
            #pragma unroll
            for (int q = 0; q < 4; q++) fma2(acc2[q], wsu[h*4+q], e2);
        }
        float* M = g_MT[which];
        int dd = tid>>1, lo = tid&1;
        #pragma unroll
        for (int q = 0; q < 4; q++){
            float2 f = up2(acc2[q]);
            M[dd*4096 + (g0+q*2)*2 + lo]   = f.x;
            M[dd*4096 + (g0+q*2+1)*2 + lo] = f.y;
        }
    }
}

// xg for 16 rows (same t) per block; writes [t][g][b]
__global__ void k_xg(const int* __restrict__ idxs, int sstride,
                     const float* __restrict__ wv,
                     const float* __restrict__ bih, const float* __restrict__ bhh,
                     int which){
    __shared__ __align__(16) float wvs[16*304];
    __shared__ int sidx[16];
    int tid = threadIdx.x;
    int row16 = blockIdx.x*16, t = row16>>5, b0 = row16&31;
    if (tid < 16) sidx[tid] = idxs[(b0+tid)*sstride + t];
    __syncthreads();
    const float4* wv4 = (const float4*)wv;
    for (int i = tid; i < 1200; i += 256){
        int r = i/75, d4 = i - r*75;
        *(float4*)&wvs[r*304 + d4*4] = wv4[(size_t)sidx[r]*75 + d4];
    }
    __syncthreads();
    const unsigned long long* Mu = (const unsigned long long*)g_MT[which];
    const unsigned long long* wu = (const unsigned long long*)wvs;
    float* xg = which ? g_xgD : g_xgE;
    for (int pass = 0; pass < 4; pass++){
        unsigned long long a0[16], a1[16];
        #pragma unroll
        for (int r = 0; r < 16; r++){ a0[r] = 0ULL; a1[r] = 0ULL; }
        int g = pass*512 + tid;
        for (int dd = 0; dd < 150; dd++){
            unsigned long long m0 = Mu[dd*2048 + g];
            unsigned long long m1 = Mu[dd*2048 + g + 256];
            #pragma unroll
            for (int r = 0; r < 16; r++){
                unsigned long long w2 = wu[r*152 + dd];
                fma2(a0[r], m0, w2);
                fma2(a1[r], m1, w2);
            }
        }
        float bs0 = bih[g] + bhh[g], bs1 = bih[g+256] + bhh[g+256];
        size_t base0 = ((size_t)t*Gg + g)*Bb + b0;
        size_t base1 = ((size_t)t*Gg + g + 256)*Bb + b0;
        #pragma unroll
        for (int r = 0; r < 16; r++){
            float2 f0 = up2(a0[r]), f1 = up2(a1[r]);
            xg[base0 + r] = f0.x + f0.y + bs0;
            xg[base1 + r] = f1.x + f1.y + bs1;
        }
    }
}

// ---------------- persistent LSTM ----------------
#define HS_OFF   (16*512)
#define HS_SZ    (128*33*4)
#define SACC_OFF (HS_OFF + HS_SZ)
#define SMEM_PERSIST ((SACC_OFF + 512)*4)

__global__ void __launch_bounds__(256, 1)
k_persist(const float* __restrict__ whh, int which, int nsteps, int p0,
          int use_mask, int store_dech, unsigned bar_base){
    extern __shared__ __align__(16) float dsm[];
    float* ws = dsm;
    float* hs = dsm + HS_OFF;
    float* sacc = dsm + SACC_OFF;
    int tid = threadIdx.x, kg = blockIdx.x, k0 = kg*4;

    // stage Whh rows once: row rr = gate*4 + klocal
    const float4* w4 = (const float4*)whh;
    float4* ws4 = (float4*)ws;
    for (int i = tid; i < 2048; i += 256){
        int rr = i>>7, j4 = i&127;
        ws4[i] = w4[(size_t)((rr>>2)*Hh + k0 + (rr&3))*128 + j4];
    }

    int b = tid&31;
    float c_reg = 0.f, h_own = 0.f;
    int mylen = 0x7fffffff, k = 0, kk = 0;
    if (tid < 128){
        kk = tid>>5; k = k0 + kk;
        c_reg = g_c[k*32 + b];
        h_own = g_h[p0][kg*128 + b*4 + kk];
        if (use_mask) mylen = g_clen[b];
    }
    const float* xg = which ? g_xgD : g_xgE;
    int rr2 = tid>>5, r0 = rr2*2;
    const ulonglong2* wsU = (const ulonglong2*)ws;
    ulonglong2* hsU = (ulonglong2*)hs;
    __syncthreads();

    int p = p0;
    for (int t = 0; t < nsteps; t++){
        // prefetch xg[t] (DRAM) overlapping stage + GEMV
        float pvi = 0.f, pvf = 0.f, pvg = 0.f, pvo = 0.f;
        if (tid < 128){
            size_t xb = ((size_t)t*Gg + k)*Bb + b;
            pvi = __ldg(&xg[xb]);
            pvf = __ldg(&xg[xb + 512*Bb]);
            pvg = __ldg(&xg[xb + 1024*Bb]);
            pvo = __ldg(&xg[xb + 1536*Bb]);
        }

        // stage h(p) into smem (L2-coherent reads)
        const ulonglong2* hg = (const ulonglong2*)g_h[p];
        for (int i = tid; i < 4096; i += 256)
            hsU[(i>>5)*33 + (i&31)] = ldcg128(&hg[i]);
        __syncthreads();

        // gates GEMV: rows r0, r0+1 (of 16), batch b
        unsigned long long a0 = 0ULL, a1 = 0ULL;
        #pragma unroll 4
        for (int jj4 = 0; jj4 < 128; jj4++){
            ulonglong2 hv = hsU[jj4*33 + b];
            ulonglong2 w0 = wsU[r0*128 + jj4];
            ulonglong2 w1 = wsU[(r0+1)*128 + jj4];
            fma2(a0, w0.x, hv.x); fma2(a0, w0.y, hv.y);
            fma2(a1, w1.x, hv.x); fma2(a1, w1.y, hv.y);
        }
        float2 f0 = up2(a0), f1 = up2(a1);
        sacc[r0*32 + b] = f0.x + f0.y;
        sacc[(r0+1)*32 + b] = f1.x + f1.y;
        __syncthreads();

        if (tid < 128){
            float vi = pvi + sacc[(0*4+kk)*32 + b];
            float vf = pvf + sacc[(1*4+kk)*32 + b];
            float vg = pvg + sacc[(2*4+kk)*32 + b];
            float vo = pvo + sacc[(3*4+kk)*32 + b];
            float ig = 1.f/(1.f + expf(-vi));
            float fg = 1.f/(1.f + expf(-vf));
            float gg = tanhf(vg);
            float og = 1.f/(1.f + expf(-vo));
            float nc = fg*c_reg + ig*gg;
            float nh = og*tanhf(nc);
            if (t < mylen){ c_reg = nc; h_own = nh; }
            g_h[p^1][kg*128 + b*4 + kk] = h_own;
            if (store_dech) g_dech[(size_t)(b*LQ1 + t)*Hh + k] = h_own;
        }
        __syncthreads();

        // grid barrier: one fence per block per side
        if (tid == 0){
            unsigned target = bar_base + (unsigned)t + 1u;
            __threadfence();                              // release block's stores
            unsigned old = atomicAdd(&g_bar_count, 1u);
            if (old + 1u == target*GRIDP){
                __threadfence();                          // order observed arrivals before sense
                atomicExch(&g_bar_sense, target);
            } else {
                while (ldvol(&g_bar_sense) < target) {}
            }
            __threadfence();                              // acquire side
        }
        __syncthreads();
        p ^= 1;
    }
    if (tid < 128) g_c[k*32 + b] = c_reg;
}

// GEMM: block = 64 rows x 128 v; thread = 8 rows x 4 v (FMA2 over k pairs)
__global__ void __launch_bounds__(256)
k_proj(const float* __restrict__ pW, const float* __restrict__ pb,
       float* __restrict__ out){
    __shared__ __align__(16) float As[64*36];
    __shared__ __align__(16) float Bs[128*36];
    int tid = threadIdx.x;
    int row0 = blockIdx.x*64, v0 = blockIdx.y*128;
    int vg = tid&31, rgrp = tid>>5;
    unsigned long long acc[8][4];
    #pragma unroll
    for (int r = 0; r < 8; r++)
        #pragma unroll
        for (int v = 0; v < 4; v++) acc[r][v] = 0ULL;
    const float4* pW4 = (const float4*)pW;
    for (int kc = 0; kc < Hh; kc += 32){
        __syncthreads();
        for (int i = tid; i < 2048; i += 256)
            As[(i>>5)*36 + (i&31)] = g_dech[(size_t)(row0 + (i>>5))*Hh + kc + (i&31)];
        for (int i = tid; i < 1024; i += 256){
            int vv = i>>3, q = i&7, v = v0 + vv;
            float4 val = (v < Vv) ? pW4[(size_t)v*128 + (kc>>2) + q]
                                  : make_float4(0.f,0.f,0.f,0.f);
            ulonglong2* dst = (ulonglong2*)Bs + (size_t)vv*9 + q;
            *dst = *(const ulonglong2*)&val;
        }
        __syncthreads();
        const ulonglong2* Au = (const ulonglong2*)As;
        const ulonglong2* Bu = (const ulonglong2*)Bs;
        #pragma unroll
        for (int kk2 = 0; kk2 < 8; kk2++){
            ulonglong2 a2[8], b2[4];
            #pragma unroll
            for (int r = 0; r < 8; r++) a2[r] = Au[(rgrp*8 + r)*9 + kk2];
            #pragma unroll
            for (int v = 0; v < 4; v++) b2[v] = Bu[(vg + 32*v)*9 + kk2];
            #pragma unroll
            for (int r = 0; r < 8; r++)
                #pragma unroll
                for (int v = 0; v < 4; v++){
                    fma2(acc[r][v], a2[r].x, b2[v].x);
                    fma2(acc[r][v], a2[r].y, b2[v].y);
                }
        }
    }
    #pragma unroll
    for (int r = 0; r < 8; r++){
        int row = row0 + rgrp*8 + r;
        if (row < NR){
            #pragma unroll
            for (int v = 0; v < 4; v++){
                int vc = v0 + vg + 32*v;
                if (vc < Vv){
                    float2 f = up2(acc[r][v]);
                    out[(size_t)row*Vv + vc] = f.x + f.y + pb[vc];
                }
            }
        }
    }
}

__global__ void k_softmax(const int* __restrict__ qw, float* __restrict__ out){
    int row = blockIdx.x, tid = threadIdx.x;
    int b = row/LQ1, t = row - b*LQ1;
    float* p = out + (size_t)row*Vv;
    float4* p4 = (float4*)p;
    if (qw[b*30 + t] == 0){
        float4 fill = make_float4(NEGLOGV, NEGLOGV, NEGLOGV, NEGLOGV);
        for (int i = tid; i < 12500; i += 256) p4[i] = fill;
        return;
    }
    __shared__ float red[256];
    float m = -1e30f;
    for (int i = tid; i < 12500; i += 256){
        float4 x = p4[i];
        m = fmaxf(m, fmaxf(fmaxf(x.x, x.y), fmaxf(x.z, x.w)));
    }
    red[tid] = m; __syncthreads();
    for (int s = 128; s > 0; s >>= 1){
        if (tid < s) red[tid] = fmaxf(red[tid], red[tid+s]);
        __syncthreads();
    }
    m = red[0]; __syncthreads();
    float sum = 0.f;
    for (int i = tid; i < 12500; i += 256){
        float4 x = p4[i];
        sum += __expf(x.x - m) + __expf(x.y - m) + __expf(x.z - m) + __expf(x.w - m);
    }
    red[tid] = sum; __syncthreads();
    for (int s = 128; s > 0; s >>= 1){
        if (tid < s) red[tid] += red[tid+s];
        __syncthreads();
    }
    float lse = m + logf(red[0]);
    __syncthreads();
    for (int i = tid; i < 12500; i += 256){
        float4 x = p4[i];
        x.x -= lse; x.y -= lse; x.z -= lse; x.w -= lse;
        p4[i] = x;
    }
}

extern "C" void kernel_launch(void* const* d_in, const int* in_sizes, int n_in,
                              void* d_out, int out_size){
    const int*   cw   = (const int*)d_in[0];
    const int*   qw   = (const int*)d_in[1];
    const float* wv   = (const float*)d_in[2];
    const float* embW = (const float*)d_in[3];
    const float* eWih = (const float*)d_in[4];
    const float* eWhh = (const float*)d_in[5];
    const float* ebih = (const float*)d_in[6];
    const float* ebhh = (const float*)d_in[7];
    const float* dWih = (const float*)d_in[8];
    const float* dWhh = (const float*)d_in[9];
    const float* dbih = (const float*)d_in[10];
    const float* dbhh = (const float*)d_in[11];
    const float* pW   = (const float*)d_in[12];
    const float* pb   = (const float*)d_in[13];
    float* out = (float*)d_out;

    static int smem_set = 0;
    if (!smem_set){
        cudaFuncSetAttribute(k_persist, cudaFuncAttributeMaxDynamicSharedMemorySize, SMEM_PERSIST);
        smem_set = 1;
    }

    k_clen<<<1, 256>>>(cw);
    k_zero<<<64, 256>>>();
    k_fuseM<<<256, 320>>>(eWih, embW, 0);
    k_fuseM<<<256, 320>>>(dWih, embW, 1);
    k_xg<<<800, 256>>>(cw, LCc, wv, ebih, ebhh, 0);
    k_xg<<<58, 256>>>(qw, 30, wv, dbih, dbhh, 1);
    k_persist<<<128, 256, SMEM_PERSIST>>>(eWhh, 0, LCc, 0, 1, 0, 0u);
    k_persist<<<128, 256, SMEM_PERSIST>>>(dWhh, 1, LQ1, LCc & 1, 0, 1, (unsigned)LCc);
    k_proj<<<dim3(15, 391), 256>>>(pW, pb, out);
    k_softmax<<<NR, 256>>>(qw, out);
}

// round 16
// speedup vs baseline: 2.1245x; 1.1172x over previous
#include <cuda_runtime.h>
#include <cstdint>

#define Vv 50000
#define Dd 300
#define Hh 512
#define Gg 2048
#define Bb 32
#define LCc 400
#define LQ1 29
#define NR 928
#define NRPAD 960
#define NEGLOGV -10.8197782844103f

// ---------------- device scratch ----------------
__device__ __align__(16) float g_MT[2][150*4096];            // [which][d/2][g][d&1]
__device__ __align__(16) float g_xgE[(size_t)LCc*Gg*Bb];     // [t][g][b]
__device__ __align__(16) float g_xgD[(size_t)LQ1*Gg*Bb];     // [t][g][b]
__device__ __align__(16) float g_h[2][Bb*Hh];                // [b][k]
__device__ __align__(16) float g_c[Hh*Bb];                   // [k*32+b]
__device__ __align__(16) float g_dech[(size_t)NRPAD*Hh];     // [(b*29+t)][k]
__device__ int g_clen[Bb];
__device__ unsigned g_bar1[8*32];                            // group counters, 128B apart
__device__ unsigned g_bar2;
__device__ unsigned g_bar_sense;

// ---------------- helpers ----------------
__device__ __forceinline__ void fma2(unsigned long long &a, unsigned long long x, unsigned long long y){
    asm("fma.rn.f32x2 %0, %1, %2, %0;" : "+l"(a) : "l"(x), "l"(y));
}
__device__ __forceinline__ float2 up2(unsigned long long v){
    float2 f; asm("mov.b64 {%0,%1}, %2;" : "=f"(f.x), "=f"(f.y) : "l"(v)); return f;
}
__device__ __forceinline__ unsigned long long pack2(float x){
    unsigned long long r; asm("mov.b64 %0, {%1, %1};" : "=l"(r) : "f"(x)); return r;
}
__device__ __forceinline__ ulonglong2 ldcg128(const ulonglong2* p){
    ulonglong2 r;
    asm volatile("ld.global.cg.v2.u64 {%0,%1},[%2];" : "=l"(r.x), "=l"(r.y) : "l"(p));
    return r;
}
__device__ __forceinline__ unsigned ldvol(const unsigned* p){
    unsigned v;
    asm volatile("ld.volatile.global.u32 %0,[%1];" : "=r"(v) : "l"(p));
    return v;
}

__global__ void k_clen(const int* __restrict__ cw){
    int tid = threadIdx.x, b = tid>>3, sub = tid&7, s = 0;
    for (int t = sub; t < LCc; t += 8) s += (cw[b*LCc+t] != 0);
    __shared__ int r[256];
    r[tid] = s; __syncthreads();
    if (sub == 0){ int tot = 0;
        #pragma unroll
        for (int u = 0; u < 8; u++) tot += r[tid+u];
        g_clen[b] = tot; }
}

__global__ void k_zero(){
    int i = blockIdx.x*256 + threadIdx.x;
    if (i < Bb*Hh){ g_h[0][i] = 0.f; g_h[1][i] = 0.f; g_c[i] = 0.f; }
    if (i < 256){ g_bar1[i] = 0u; }
    if (i == 0){ g_bar2 = 0u; g_bar_sense = 0u; }
}

// M[g][d] = sum_h Wih[g][h]*embW[h][d], g-pair FMA2, smem layout [h][g]
__global__ void k_fuseM(const float* __restrict__ Wih, const float* __restrict__ embW, int which){
    __shared__ __align__(16) float ws[512*8];
    int tid = threadIdx.x, g0 = blockIdx.x*8;
    for (int i = tid; i < 4096; i += 320)
        ws[(i&511)*8 + (i>>9)] = Wih[(size_t)(g0 + (i>>9))*Hh + (i&511)];
    __syncthreads();
    if (tid < Dd){
        unsigned long long acc2[4] = {0ULL,0ULL,0ULL,0ULL};
        const unsigned long long* wsu = (const unsigned long long*)ws;
        for (int h = 0; h < Hh; h++){
            unsigned long long e2 = pack2(embW[h*Dd + tid]);
            #pragma unroll
            for (int q = 0; q < 4; q++) fma2(acc2[q], wsu[h*4+q], e2);
        }
        float* M = g_MT[which];
        int dd = tid>>1, lo = tid&1;
        #pragma unroll
        for (int q = 0; q < 4; q++){
            float2 f = up2(acc2[q]);
            M[dd*4096 + (g0+q*2)*2 + lo]   = f.x;
            M[dd*4096 + (g0+q*2+1)*2 + lo] = f.y;
        }
    }
}

// xg for 16 rows (same t) per block; writes [t][g][b]
__global__ void k_xg(const int* __restrict__ idxs, int sstride,
                     const float* __restrict__ wv,
                     const float* __restrict__ bih, const float* __restrict__ bhh,
                     int which){
    __shared__ __align__(16) float wvs[16*304];
    __shared__ int sidx[16];
    int tid = threadIdx.x;
    int row16 = blockIdx.x*16, t = row16>>5, b0 = row16&31;
    if (tid < 16) sidx[tid] = idxs[(b0+tid)*sstride + t];
    __syncthreads();
    const float4* wv4 = (const float4*)wv;
    for (int i = tid; i < 1200; i += 256){
        int r = i/75, d4 = i - r*75;
        *(float4*)&wvs[r*304 + d4*4] = wv4[(size_t)sidx[r]*75 + d4];
    }
    __syncthreads();
    const unsigned long long* Mu = (const unsigned long long*)g_MT[which];
    const unsigned long long* wu = (const unsigned long long*)wvs;
    float* xg = which ? g_xgD : g_xgE;
    for (int pass = 0; pass < 4; pass++){
        unsigned long long a0[16], a1[16];
        #pragma unroll
        for (int r = 0; r < 16; r++){ a0[r] = 0ULL; a1[r] = 0ULL; }
        int g = pass*512 + tid;
        for (int dd = 0; dd < 150; dd++){
            unsigned long long m0 = Mu[dd*2048 + g];
            unsigned long long m1 = Mu[dd*2048 + g + 256];
            #pragma unroll
            for (int r = 0; r < 16; r++){
                unsigned long long w2 = wu[r*152 + dd];
                fma2(a0[r], m0, w2);
                fma2(a1[r], m1, w2);
            }
        }
        float bs0 = bih[g] + bhh[g], bs1 = bih[g+256] + bhh[g+256];
        size_t base0 = ((size_t)t*Gg + g)*Bb + b0;
        size_t base1 = ((size_t)t*Gg + g + 256)*Bb + b0;
        #pragma unroll
        for (int r = 0; r < 16; r++){
            float2 f0 = up2(a0[r]), f1 = up2(a1[r]);
            xg[base0 + r] = f0.x + f0.y + bs0;
            xg[base1 + r] = f1.x + f1.y + bs1;
        }
    }
}

// ---------------- persistent LSTM ----------------
// stride 516 floats (2064B): 16B-aligned, rows 16B apart in bank space.
#define PSTR   516
#define WS_F   (16*PSTR)
#define HS_F   (32*PSTR)
#define HS_OFF WS_F
#define SACC_OFF (WS_F + HS_F)
#define SACC_F (4*16*33)
#define SMEM_PERSIST ((WS_F + HS_F + SACC_F)*4)

__global__ void __launch_bounds__(256, 1)
k_persist(const float* __restrict__ whh, int which, int nsteps, int p0,
          int use_mask, int store_dech, unsigned bar_base){
    extern __shared__ __align__(16) float dsm[];
    float* ws = dsm;
    float* hs = dsm + HS_OFF;
    float* sacc = dsm + SACC_OFF;
    int tid = threadIdx.x, kg = blockIdx.x, k0 = kg*4;

    // stage Whh rows once, permuted: logical row rr = gate*4+klocal stored at
    // sigma(rr) = (rr&3)*4 + (rr>>2) so warp-sets {r,4+r,8+r,12+r} are consecutive.
    const float4* w4 = (const float4*)whh;
    for (int i = tid; i < 2048; i += 256){
        int rr = i>>7, j4 = i&127;
        int sig = (rr&3)*4 + (rr>>2);
        *(float4*)&ws[sig*PSTR + j4*4] = w4[(size_t)((rr>>2)*Hh + k0 + (rr&3))*128 + j4];
    }

    int b = tid&31;
    float c_reg = 0.f, h_own = 0.f;
    int mylen = 0x7fffffff, k = 0, kk = 0;
    if (tid < 128){
        kk = tid>>5; k = k0 + kk;
        c_reg = g_c[k*32 + b];
        h_own = g_h[p0][b*Hh + k];
        if (use_mask) mylen = g_clen[b];
    }
    // GEMV mapping: warp = (j-split js, batch-half bw); lane = (rgrp, bgrp)
    // lane handles batches b0 = bw*16+bgrp and b0+8 (step-1 row sets => conflict-free)
    int wid = tid>>5, lane = tid&31;
    int js = wid & 3, bw = wid >> 2;
    int rgrp = lane >> 3, bgrp = lane & 7;
    int bA = bw*16 + bgrp;
    int jbase = js*128;
    const float* xg = which ? g_xgD : g_xgE;
    __syncthreads();

    int p = p0;
    for (int t = 0; t < nsteps; t++){
        // prefetch xg[t] (DRAM) overlapping stage + GEMV
        float pvi = 0.f, pvf = 0.f, pvg = 0.f, pvo = 0.f;
        if (tid < 128){
            size_t xb = ((size_t)t*Gg + k)*Bb + b;
            pvi = __ldg(&xg[xb]);
            pvf = __ldg(&xg[xb + 512*Bb]);
            pvg = __ldg(&xg[xb + 1024*Bb]);
            pvo = __ldg(&xg[xb + 1536*Bb]);
        }

        // stage h(p): [b][k] global -> [b][PSTR] smem
        const ulonglong2* hg = (const ulonglong2*)g_h[p];
        for (int i = tid; i < 4096; i += 256){
            int bb = i>>7, k4 = i&127;
            *(ulonglong2*)&hs[bb*PSTR + k4*4] = ldcg128(&hg[i]);
        }
        __syncthreads();

        // GEMV: 4 logical rows (rgrp*4+r) x 2 batches (bA, bA+8) x 128 j
        unsigned long long acc[4][2];
        #pragma unroll
        for (int r = 0; r < 4; r++){ acc[r][0] = 0ULL; acc[r][1] = 0ULL; }
        #pragma unroll 2
        for (int it = 0; it < 32; it++){
            int j4 = jbase + it*4;
            ulonglong2 h0 = *(const ulonglong2*)&hs[bA*PSTR + j4];
            ulonglong2 h1 = *(const ulonglong2*)&hs[(bA+8)*PSTR + j4];
            #pragma unroll
            for (int r = 0; r < 4; r++){
                ulonglong2 wv = *(const ulonglong2*)&ws[(r*4 + rgrp)*PSTR + j4];
                fma2(acc[r][0], wv.x, h0.x); fma2(acc[r][0], wv.y, h0.y);
                fma2(acc[r][1], wv.x, h1.x); fma2(acc[r][1], wv.y, h1.y);
            }
        }
        #pragma unroll
        for (int r = 0; r < 4; r++){
            float2 f0 = up2(acc[r][0]), f1 = up2(acc[r][1]);
            sacc[(js*16 + rgrp*4 + r)*33 + bA]     = f0.x + f0.y;
            sacc[(js*16 + rgrp*4 + r)*33 + bA + 8] = f1.x + f1.y;
        }
        __syncthreads();

        if (tid < 128){
            float vi = pvi, vf = pvf, vg = pvg, vo = pvo;
            #pragma unroll
            for (int q = 0; q < 4; q++){
                vi += sacc[(q*16 + 0*4 + kk)*33 + b];
                vf += sacc[(q*16 + 1*4 + kk)*33 + b];
                vg += sacc[(q*16 + 2*4 + kk)*33 + b];
                vo += sacc[(q*16 + 3*4 + kk)*33 + b];
            }
            float ig = 1.f/(1.f + expf(-vi));
            float fg = 1.f/(1.f + expf(-vf));
            float gg = tanhf(vg);
            float og = 1.f/(1.f + expf(-vo));
            float nc = fg*c_reg + ig*gg;
            float nh = og*tanhf(nc);
            if (t < mylen){ c_reg = nc; h_own = nh; }
            g_h[p^1][b*Hh + k] = h_own;
            if (store_dech) g_dech[(size_t)(b*LQ1 + t)*Hh + k] = h_own;
        }
        __syncthreads();

        // two-level grid barrier (cumulative counts)
        if (tid == 0){
            unsigned target = bar_base + (unsigned)t + 1u;
            __threadfence();
            unsigned old = atomicAdd(&g_bar1[(kg>>4)*32], 1u);
            if (old + 1u == target*16u){
                unsigned o2 = atomicAdd(&g_bar2, 1u);
                if (o2 + 1u == target*8u){
                    atomicExch(&g_bar_sense, target);
                } else {
                    while (ldvol(&g_bar_sense) < target) {}
                }
            } else {
                while (ldvol(&g_bar_sense) < target) {}
            }
            __threadfence();
        }
        __syncthreads();
        p ^= 1;
    }
    if (tid < 128) g_c[k*32 + b] = c_reg;
}

// GEMM: block = 64 rows x 128 v; thread = 8 rows x 4 v (FMA2 over k pairs)
__global__ void __launch_bounds__(256)
k_proj(const float* __restrict__ pW, const float* __restrict__ pb,
       float* __restrict__ out){
    __shared__ __align__(16) float As[64*36];
    __shared__ __align__(16) float Bs[128*36];
    int tid = threadIdx.x;
    int row0 = blockIdx.x*64, v0 = blockIdx.y*128;
    int vg = tid&31, rgrp = tid>>5;
    unsigned long long acc[8][4];
    #pragma unroll
    for (int r = 0; r < 8; r++)
        #pragma unroll
        for (int v = 0; v < 4; v++) acc[r][v] = 0ULL;
    const float4* pW4 = (const float4*)pW;
    for (int kc = 0; kc < Hh; kc += 32){
        __syncthreads();
        for (int i = tid; i < 2048; i += 256)
            As[(i>>5)*36 + (i&31)] = g_dech[(size_t)(row0 + (i>>5))*Hh + kc + (i&31)];
        for (int i = tid; i < 1024; i += 256){
            int vv = i>>3, q = i&7, v = v0 + vv;
            float4 val = (v < Vv) ? pW4[(size_t)v*128 + (kc>>2) + q]
                                  : make_float4(0.f,0.f,0.f,0.f);
            ulonglong2* dst = (ulonglong2*)Bs + (size_t)vv*9 + q;
            *dst = *(const ulonglong2*)&val;
        }
        __syncthreads();
        const ulonglong2* Au = (const ulonglong2*)As;
        const ulonglong2* Bu = (const ulonglong2*)Bs;
        #pragma unroll
        for (int kk2 = 0; kk2 < 8; kk2++){
            ulonglong2 a2[8], b2[4];
            #pragma unroll
            for (int r = 0; r < 8; r++) a2[r] = Au[(rgrp*8 + r)*9 + kk2];
            #pragma unroll
            for (int v = 0; v < 4; v++) b2[v] = Bu[(vg + 32*v)*9 + kk2];
            #pragma unroll
            for (int r = 0; r < 8; r++)
                #pragma unroll
                for (int v = 0; v < 4; v++){
                    fma2(acc[r][v], a2[r].x, b2[v].x);
                    fma2(acc[r][v], a2[r].y, b2[v].y);
                }
        }
    }
    #pragma unroll
    for (int r = 0; r < 8; r++){
        int row = row0 + rgrp*8 + r;
        if (row < NR){
            #pragma unroll
            for (int v = 0; v < 4; v++){
                int vc = v0 + vg + 32*v;
                if (vc < Vv){
                    float2 f = up2(acc[r][v]);
                    out[(size_t)row*Vv + vc] = f.x + f.y + pb[vc];
                }
            }
        }
    }
}

__global__ void k_softmax(const int* __restrict__ qw, float* __restrict__ out){
    int row = blockIdx.x, tid = threadIdx.x;
    int b = row/LQ1, t = row - b*LQ1;
    float* p = out + (size_t)row*Vv;
    float4* p4 = (float4*)p;
    if (qw[b*30 + t] == 0){
        float4 fill = make_float4(NEGLOGV, NEGLOGV, NEGLOGV, NEGLOGV);
        for (int i = tid; i < 12500; i += 256) p4[i] = fill;
        return;
    }
    __shared__ float red[256];
    float m = -1e30f;
    for (int i = tid; i < 12500; i += 256){
        float4 x = p4[i];
        m = fmaxf(m, fmaxf(fmaxf(x.x, x.y), fmaxf(x.z, x.w)));
    }
    red[tid] = m; __syncthreads();
    for (int s = 128; s > 0; s >>= 1){
        if (tid < s) red[tid] = fmaxf(red[tid], red[tid+s]);
        __syncthreads();
    }
    m = red[0]; __syncthreads();
    float sum = 0.f;
    for (int i = tid; i < 12500; i += 256){
        float4 x = p4[i];
        sum += __expf(x.x - m) + __expf(x.y - m) + __expf(x.z - m) + __expf(x.w - m);
    }
    red[tid] = sum; __syncthreads();
    for (int s = 128; s > 0; s >>= 1){
        if (tid < s) red[tid] += red[tid+s];
        __syncthreads();
    }
    float lse = m + logf(red[0]);
    __syncthreads();
    for (int i = tid; i < 12500; i += 256){
        float4 x = p4[i];
        x.x -= lse; x.y -= lse; x.z -= lse; x.w -= lse;
        p4[i] = x;
    }
}

extern "C" void kernel_launch(void* const* d_in, const int* in_sizes, int n_in,
                              void* d_out, int out_size){
    const int*   cw   = (const int*)d_in[0];
    const int*   qw   = (const int*)d_in[1];
    const float* wv   = (const float*)d_in[2];
    const float* embW = (const float*)d_in[3];
    const float* eWih = (const float*)d_in[4];
    const float* eWhh = (const float*)d_in[5];
    const float* ebih = (const float*)d_in[6];
    const float* ebhh = (const float*)d_in[7];
    const float* dWih = (const float*)d_in[8];
    const float* dWhh = (const float*)d_in[9];
    const float* dbih = (const float*)d_in[10];
    const float* dbhh = (const float*)d_in[11];
    const float* pW   = (const float*)d_in[12];
    const float* pb   = (const float*)d_in[13];
    float* out = (float*)d_out;

    static int smem_set = 0;
    if (!smem_set){
        cudaFuncSetAttribute(k_persist, cudaFuncAttributeMaxDynamicSharedMemorySize, SMEM_PERSIST);
        smem_set = 1;
    }

    k_clen<<<1, 256>>>(cw);
    k_zero<<<64, 256>>>();
    k_fuseM<<<256, 320>>>(eWih, embW, 0);
    k_fuseM<<<256, 320>>>(dWih, embW, 1);
    k_xg<<<800, 256>>>(cw, LCc, wv, ebih, ebhh, 0);
    k_xg<<<58, 256>>>(qw, 30, wv, dbih, dbhh, 1);
    k_persist<<<128, 256, SMEM_PERSIST>>>(eWhh, 0, LCc, 0, 1, 0, 0u);
    k_persist<<<128, 256, SMEM_PERSIST>>>(dWhh, 1, LQ1, LCc & 1, 0, 1, (unsigned)LCc);
    k_proj<<<dim3(15, 391), 256>>>(pW, pb, out);
    k_softmax<<<NR, 256>>>(qw, out);
}